// round 1
// baseline (speedup 1.0000x reference)
#include <cuda_runtime.h>
#include <cstdint>
#include <cstddef>

#define Bn 128
#define Tn 2048
#define Cn 128

// Scratch: all forward alphas (exact fp32) + transposed transitions.
// __device__ globals (no runtime allocation).
__device__ __align__(16) float g_alpha[(size_t)Bn * Tn * Cn];
__device__ __align__(16) float g_transT[Cn * Cn];

__device__ __forceinline__ unsigned long long pack2(float lo, float hi) {
    unsigned long long r;
    asm("mov.b64 %0, {%1, %2};" : "=l"(r) : "f"(lo), "f"(hi));
    return r;
}
__device__ __forceinline__ unsigned long long add2(unsigned long long a, unsigned long long b) {
    unsigned long long r;
    asm("add.rn.f32x2 %0, %1, %2;" : "=l"(r) : "l"(a), "l"(b));
    return r;
}
__device__ __forceinline__ float lo32(unsigned long long v) {
    return __uint_as_float((unsigned)v);
}
__device__ __forceinline__ float hi32(unsigned long long v) {
    return __uint_as_float((unsigned)(v >> 32));
}

// Exact monotone float->int key: a > b (fp, no NaN) <=> fkey(a) > fkey(b) (signed int).
__device__ __forceinline__ int fkey(float f) {
    int b = __float_as_int(f);
    return b ^ ((b >> 31) & 0x7fffffff);
}

// Warp-collective argmax over 128 values (lane l holds values for indices 4l..4l+3).
// Returns the SMALLEST index achieving the exact max (matches jnp.argmax first-max).
__device__ __forceinline__ int warp_argmax4(float4 v, int l) {
    int k0 = fkey(v.x), k1 = fkey(v.y), k2 = fkey(v.z), k3 = fkey(v.w);
    int km = max(max(k0, k1), max(k2, k3));
    int wm = __reduce_max_sync(0xffffffffu, km);
    unsigned i0 = (k0 == wm) ? (unsigned)(4 * l + 0) : 0xffffffffu;
    unsigned i1 = (k1 == wm) ? (unsigned)(4 * l + 1) : 0xffffffffu;
    unsigned i2 = (k2 == wm) ? (unsigned)(4 * l + 2) : 0xffffffffu;
    unsigned i3 = (k3 == wm) ? (unsigned)(4 * l + 3) : 0xffffffffu;
    unsigned c = min(min(i0, i1), min(i2, i3));
    return (int)__reduce_min_sync(0xffffffffu, c);
}

__global__ __launch_bounds__(Cn, 1)
void viterbi_kernel(const float* __restrict__ pot,
                    const float* __restrict__ trans,
                    float* __restrict__ out) {
    __shared__ __align__(16) float4 sbuf[2][Cn / 4];  // double-buffered alpha row

    const int b = blockIdx.x;
    const int j = threadIdx.x;

    // ---- Build transposed transitions (every CTA writes identical values: benign) ----
    #pragma unroll 8
    for (int it = 0; it < Cn; ++it) {
        g_transT[j * Cn + it] = trans[it * Cn + j];  // coalesced read, scattered write
    }

    // ---- Load transitions column j into registers, packed as f32x2 pairs ----
    unsigned long long tr2[Cn / 2];
    #pragma unroll
    for (int q = 0; q < Cn / 2; ++q) {
        float a = trans[(2 * q) * Cn + j];
        float c = trans[(2 * q + 1) * Cn + j];
        tr2[q] = pack2(a, c);
    }

    const float* potp = pot + ((size_t)b * Tn) * Cn + j;
    float* aout = g_alpha + ((size_t)b * Tn) * Cn + j;

    const float NEG_INF = __int_as_float(0xff800000);

    // ---- t = 0 ----
    float alpha = potp[0];
    ((float*)sbuf[0])[j] = alpha;
    aout[0] = alpha;

    // Prefetch ring for potentials (distance 4 steps)
    float pr[4];
    #pragma unroll
    for (int u = 0; u < 4; ++u) pr[u] = potp[(size_t)(1 + u) * Cn];

    __syncthreads();

    // ---- Forward: t = 1 .. T-1 ----
    int p = 0;
    for (int tb = 1; tb < Tn; tb += 4) {
        #pragma unroll
        for (int u = 0; u < 4; ++u) {
            int t = tb + u;
            if (t < Tn) {  // uniform across CTA
                float potv = pr[u];
                int tn = t + 4;
                if (tn < Tn) pr[u] = potp[(size_t)tn * Cn];

                float m0 = NEG_INF, m1 = NEG_INF, m2 = NEG_INF, m3 = NEG_INF;
                const float4* ab = sbuf[p];
                #pragma unroll
                for (int g = 0; g < Cn / 4; ++g) {
                    float4 a = ab[g];  // broadcast LDS.128
                    unsigned long long s01 = add2(pack2(a.x, a.y), tr2[2 * g]);
                    unsigned long long s23 = add2(pack2(a.z, a.w), tr2[2 * g + 1]);
                    m0 = fmaxf(m0, lo32(s01));
                    m1 = fmaxf(m1, hi32(s01));
                    m2 = fmaxf(m2, lo32(s23));
                    m3 = fmaxf(m3, hi32(s23));
                }
                float best = fmaxf(fmaxf(m0, m1), fmaxf(m2, m3));
                alpha = best + potv;

                ((float*)sbuf[p ^ 1])[j] = alpha;
                aout[(size_t)t * Cn] = alpha;
                __syncthreads();
                p ^= 1;
            }
        }
    }

    // ---- Backward: warp 0 traces the path for this batch ----
    if (j < 32) {
        const int l = j;
        float* ob = out + (size_t)b * Tn;

        // last tag = argmax over alpha_{T-1} (currently in sbuf[p])
        float4 av = sbuf[p][l];
        int tag = warp_argmax4(av, l);
        if (l == 0) ob[Tn - 1] = (float)tag;

        const float4* arow = (const float4*)(g_alpha + (size_t)b * Tn * Cn);
        const float4* tT = (const float4*)g_transT;

        // Prefetch alpha rows 8 deep (independent of tag chain)
        float4 pf[8];
        const int t0 = Tn - 2;
        #pragma unroll
        for (int u = 0; u < 8; ++u) {
            pf[u] = (t0 - u >= 0) ? arow[(size_t)(t0 - u) * 32 + l]
                                  : make_float4(0.f, 0.f, 0.f, 0.f);
        }

        for (int tb = t0; tb >= 0; tb -= 8) {
            #pragma unroll
            for (int u = 0; u < 8; ++u) {
                int t = tb - u;
                if (t >= 0) {
                    float4 a = pf[u];
                    if (t - 8 >= 0) pf[u] = arow[(size_t)(t - 8) * 32 + l];

                    float4 tv = tT[tag * 32 + l];  // column 'tag' of transitions
                    float4 s;
                    s.x = a.x + tv.x;
                    s.y = a.y + tv.y;
                    s.z = a.z + tv.z;
                    s.w = a.w + tv.w;
                    tag = warp_argmax4(s, l);
                    if (l == 0) ob[t] = (float)tag;
                }
            }
        }
    }
}

extern "C" void kernel_launch(void* const* d_in, const int* in_sizes, int n_in,
                              void* d_out, int out_size) {
    const float* inputs = (const float*)d_in[0];       // [B, T, C] f32
    const float* transitions = (const float*)d_in[1];  // [C, C] f32
    float* out = (float*)d_out;                        // [B, T] f32 (tags)

    viterbi_kernel<<<Bn, Cn>>>(inputs, transitions, out);
}